// round 3
// baseline (speedup 1.0000x reference)
#include <cuda_runtime.h>
#include <cuda_bf16.h>

// Problem constants (from reference)
#define BATCH  16
#define MCTRL  64
#define NCTRL  64
#define LKNOT  68      // M + P + 1
#define DEG    3
#define TOUT   256     // OUT_U == OUT_V
#define RPB    4       // u-rows per block
#define BPB    (TOUT / RPB)   // 64 blocks per batch

// ---------------------------------------------------------------------------
// Fully fused kernel: knot normalize + span find + Cox-de Boor basis +
// factorized tensor-product surface evaluation, one launch.
// Grid: BATCH*BPB blocks, 256 threads. Since the u and v parameter grids are
// identical (and the reference builds V from knot_u), thread tid's basis at
// parameter index tid serves both roles.
// ---------------------------------------------------------------------------
__global__ __launch_bounds__(256) void SurfEval_fused_kernel(
    const float4* __restrict__ ctrl,   // [B][64][64] float4 (x,y,z,w)
    const float*  __restrict__ knot_u, // [B][68]
    float*        __restrict__ out)    // [B][256][256][3]
{
    const int b   = blockIdx.x / BPB;
    const int i0  = (blockIdx.x % BPB) * RPB;
    const int tid = threadIdx.x;

    __shared__ float  U[LKNOT];
    __shared__ float4 basis_sh[TOUT];     // 4 KB
    __shared__ int    span_sh[TOUT];      // 1 KB  (stores span-3)
    __shared__ float  colsx[RPB][NCTRL];  // 1 KB each
    __shared__ float  colsy[RPB][NCTRL];
    __shared__ float  colsz[RPB][NCTRL];
    __shared__ float  s_c0, s_inv;

    // ---- knot load + cumsum + normalize ----
    if (tid < LKNOT) U[tid] = knot_u[b * LKNOT + tid];
    __syncthreads();
    if (tid == 0) {
        float acc = 0.f;
        #pragma unroll 4
        for (int i = 0; i < LKNOT; i++) { acc += U[i]; U[i] = acc; }
        s_c0  = U[0];
        s_inv = 1.f / (U[LKNOT - 1] - U[0]);
    }
    __syncthreads();
    {
        const float c0 = s_c0, inv = s_inv;
        if (tid < LKNOT) U[tid] = (U[tid] - c0) * inv;
    }
    __syncthreads();

    // ---- per-thread span + degree-3 Cox-de Boor basis at t = grid[tid] ----
    {
        const float t = (float)(1e-5 + (double)tid * ((1.0 - 2e-5) / 255.0));

        // first-occurrence argmin over masked positive differences
        const int S = LKNOT - 2 * DEG;  // 62
        float best = 1e30f;
        int   bi   = 0;
        #pragma unroll 8
        for (int s = 0; s < S; s++) {
            float d    = t - U[s + DEG];
            float cand = (d > 1e-8f) ? d : 1.0f;
            if (cand < best) { best = cand; bi = s; }
        }
        int span = bi + DEG;
        if (span > MCTRL - 1) span = MCTRL - 1;

        float Nb[DEG + 1];
        Nb[0] = 1.f;
        #pragma unroll
        for (int k = 1; k <= DEG; k++) {
            float saved = 0.f;
            #pragma unroll
            for (int r = 0; r < DEG; r++) {
                if (r >= k) break;
                float K1   = U[span + r + 1];
                float K2   = U[span + 1 - k + r];
                float temp = Nb[r] / ((K1 - t) + (t - K2));
                Nb[r]  = saved + (K1 - t) * temp;
                saved  = (t - K2) * temp;
            }
            Nb[k] = saved;
        }

        basis_sh[tid] = make_float4(Nb[0], Nb[1], Nb[2], Nb[3]);
        span_sh[tid]  = span - 3;
    }
    __syncthreads();

    // ---- Phase 1: u-contraction per (row ri, ctrl column c) ----
    {
        const int ri = tid >> 6;            // 0..3
        const int c  = tid & 63;            // 0..63
        const int i  = i0 + ri;
        const int su = span_sh[i];          // span-3
        const float4 nu = basis_sh[i];

        const float4* cp = ctrl + ((size_t)(b * MCTRL) + su) * NCTRL + c;
        float4 p0 = cp[0 * NCTRL];
        float4 p1 = cp[1 * NCTRL];
        float4 p2 = cp[2 * NCTRL];
        float4 p3 = cp[3 * NCTRL];

        colsx[ri][c] = nu.x * p0.x + nu.y * p1.x + nu.z * p2.x + nu.w * p3.x;
        colsy[ri][c] = nu.x * p0.y + nu.y * p1.y + nu.z * p2.y + nu.w * p3.y;
        colsz[ri][c] = nu.x * p0.z + nu.y * p1.z + nu.z * p2.z + nu.w * p3.z;
    }

    // v-basis for this thread's output column (registers, reused RPB times)
    const int j = tid;
    const float4 nv = basis_sh[j];
    const int sj = span_sh[j];

    __syncthreads();

    // ---- Phase 2: v-contraction + direct coalesced-enough stores ----
    #pragma unroll
    for (int ri = 0; ri < RPB; ri++) {
        float x = nv.x * colsx[ri][sj]     + nv.y * colsx[ri][sj + 1]
                + nv.z * colsx[ri][sj + 2] + nv.w * colsx[ri][sj + 3];
        float y = nv.x * colsy[ri][sj]     + nv.y * colsy[ri][sj + 1]
                + nv.z * colsy[ri][sj + 2] + nv.w * colsy[ri][sj + 3];
        float z = nv.x * colsz[ri][sj]     + nv.y * colsz[ri][sj + 1]
                + nv.z * colsz[ri][sj + 2] + nv.w * colsz[ri][sj + 3];

        float* o = out + ((size_t)((b * TOUT) + i0 + ri) * TOUT + j) * 3;
        o[0] = x;
        o[1] = y;
        o[2] = z;
    }
}

// ---------------------------------------------------------------------------
// Launch. Inputs: d_in[0]=ctrl_pts [16,64,64,4] f32, d_in[1]=knot_u [16,68],
// d_in[2]=knot_v (UNUSED — reference builds V from knot_u).
// Output: [16,256,256,3] f32.
// ---------------------------------------------------------------------------
extern "C" void kernel_launch(void* const* d_in, const int* in_sizes, int n_in,
                              void* d_out, int out_size)
{
    const float4* ctrl   = (const float4*)d_in[0];
    const float*  knot_u = (const float*) d_in[1];
    float*        out    = (float*)d_out;

    SurfEval_fused_kernel<<<BATCH * BPB, TOUT>>>(ctrl, knot_u, out);
}

// round 4
// speedup vs baseline: 1.1604x; 1.1604x over previous
#include <cuda_runtime.h>
#include <cuda_bf16.h>

// Problem constants (from reference)
#define BATCH  16
#define MCTRL  64
#define NCTRL  64
#define LKNOT  68      // M + P + 1
#define DEG    3
#define TOUT   256     // OUT_U == OUT_V
#define RPB    4       // u-rows per block
#define BPB    (TOUT / RPB)   // 64 blocks per batch

// Span binary search: count of leading 'true' of monotone predicate
//   pred(s) = (traw - U[s+DEG] > thr),  s in [0, 62)
// reference argmin(first-occurrence) over masked diffs == last true index,
// or 0 when none true.  Returns span = bi + DEG.
__device__ __forceinline__ int find_span(const float* __restrict__ U,
                                         float traw, float thr)
{
    int c = 0;
    #pragma unroll
    for (int step = 32; step >= 1; step >>= 1) {
        int nc = c + step;
        if (nc <= 62 && (traw - U[nc - 1 + DEG]) > thr) c = nc;
    }
    int bi = c - 1;
    if (bi < 0) bi = 0;
    int span = bi + DEG;
    if (span > MCTRL - 1) span = MCTRL - 1;
    return span;
}

// Degree-3 Cox-de Boor on (possibly unnormalized) knots — affine invariant.
__device__ __forceinline__ float4 cox_de_boor(const float* __restrict__ U,
                                              float t, int span)
{
    float Nb[DEG + 1];
    Nb[0] = 1.f;
    #pragma unroll
    for (int k = 1; k <= DEG; k++) {
        float saved = 0.f;
        #pragma unroll
        for (int r = 0; r < DEG; r++) {
            if (r >= k) break;
            float K1   = U[span + r + 1];
            float K2   = U[span + 1 - k + r];
            float temp = Nb[r] / ((K1 - t) + (t - K2));
            Nb[r]  = saved + (K1 - t) * temp;
            saved  = (t - K2) * temp;
        }
        Nb[k] = saved;
    }
    return make_float4(Nb[0], Nb[1], Nb[2], Nb[3]);
}

// ---------------------------------------------------------------------------
// Fused kernel: parallel knot cumsum + span binary-search + Cox-de Boor +
// factorized tensor-product evaluation. Single launch.
// u and v grids are identical (reference builds V from knot_u too), so thread
// tid's basis at parameter index tid serves as the v-basis directly (regs).
// ---------------------------------------------------------------------------
__global__ __launch_bounds__(256) void SurfEval_fused_kernel(
    const float4* __restrict__ ctrl,   // [B][64][64] float4 (x,y,z,w)
    const float*  __restrict__ knot_u, // [B][68]
    float*        __restrict__ out)    // [B][256][256][3]
{
    const int b    = blockIdx.x / BPB;
    const int i0   = (blockIdx.x % BPB) * RPB;
    const int tid  = threadIdx.x;
    const int lane = tid & 31;
    const int wid  = tid >> 5;

    __shared__ float  U[LKNOT];
    __shared__ float  warpsum[2];
    __shared__ float4 basis_sh[TOUT];     // 4 KB (only 4 rows read back)
    __shared__ float  colsx[RPB][NCTRL];
    __shared__ float  colsy[RPB][NCTRL];
    __shared__ float  colsz[RPB][NCTRL];

    // ---- parallel inclusive cumsum of 68 knot increments (raw, unnormalized)
    {
        float v = (tid < LKNOT) ? knot_u[b * LKNOT + tid] : 0.f;
        #pragma unroll
        for (int off = 1; off < 32; off <<= 1) {
            float n = __shfl_up_sync(0xffffffffu, v, off);
            if (lane >= off) v += n;
        }
        if (lane == 31 && wid < 2) warpsum[wid] = v;
        __syncthreads();
        if (wid == 1)      v += warpsum[0];
        else if (wid == 2) v += warpsum[0] + warpsum[1];
        if (tid < LKNOT) U[tid] = v;
        __syncthreads();
    }

    const float c0  = U[0];
    const float den = U[LKNOT - 1] - c0;
    const float thr = 1e-8f * den;

    // parameter value for index p, mapped into raw-knot space
    // t01 = linspace(1e-5, 1-1e-5, 256)[p];  traw = c0 + t01*den
    const float step01 = (float)((1.0 - 2e-5) / 255.0);

    // ---- phase-1 addressing: row span first, issue ctrl loads early ----
    const int ri = tid >> 6;            // 0..3
    const int cc = tid & 63;            // 0..63
    const int i  = i0 + ri;

    const float t_row = c0 + fmaf((float)i, step01, 1e-5f) * den;
    const int   srow  = find_span(U, t_row, thr) - 3;

    const float4* cp = ctrl + ((size_t)(b * MCTRL) + srow) * NCTRL + cc;
    float4 p0 = cp[0 * NCTRL];
    float4 p1 = cp[1 * NCTRL];
    float4 p2 = cp[2 * NCTRL];
    float4 p3 = cp[3 * NCTRL];

    // ---- own (v-role) span + basis, overlapped with ctrl loads in flight ----
    const float t_own = c0 + fmaf((float)tid, step01, 1e-5f) * den;
    const int   sj    = find_span(U, t_own, thr) - 3;
    const float4 nv   = cox_de_boor(U, t_own, sj + 3);

    basis_sh[tid] = nv;
    __syncthreads();

    // ---- phase 1: u-contraction for (row ri, ctrl column cc) ----
    {
        const float4 nu = basis_sh[i];
        colsx[ri][cc] = nu.x * p0.x + nu.y * p1.x + nu.z * p2.x + nu.w * p3.x;
        colsy[ri][cc] = nu.x * p0.y + nu.y * p1.y + nu.z * p2.y + nu.w * p3.y;
        colsz[ri][cc] = nu.x * p0.z + nu.y * p1.z + nu.z * p2.z + nu.w * p3.z;
    }
    __syncthreads();

    // ---- phase 2: v-contraction (basis in registers), direct stores ----
    const int j = tid;
    #pragma unroll
    for (int rr = 0; rr < RPB; rr++) {
        float x = nv.x * colsx[rr][sj]     + nv.y * colsx[rr][sj + 1]
                + nv.z * colsx[rr][sj + 2] + nv.w * colsx[rr][sj + 3];
        float y = nv.x * colsy[rr][sj]     + nv.y * colsy[rr][sj + 1]
                + nv.z * colsy[rr][sj + 2] + nv.w * colsy[rr][sj + 3];
        float z = nv.x * colsz[rr][sj]     + nv.y * colsz[rr][sj + 1]
                + nv.z * colsz[rr][sj + 2] + nv.w * colsz[rr][sj + 3];

        float* o = out + ((size_t)((b * TOUT) + i0 + rr) * TOUT + j) * 3;
        o[0] = x;
        o[1] = y;
        o[2] = z;
    }
}

// ---------------------------------------------------------------------------
// Launch. Inputs: d_in[0]=ctrl_pts [16,64,64,4] f32, d_in[1]=knot_u [16,68],
// d_in[2]=knot_v (UNUSED — reference builds V from knot_u).
// Output: [16,256,256,3] f32.
// ---------------------------------------------------------------------------
extern "C" void kernel_launch(void* const* d_in, const int* in_sizes, int n_in,
                              void* d_out, int out_size)
{
    const float4* ctrl   = (const float4*)d_in[0];
    const float*  knot_u = (const float*) d_in[1];
    float*        out    = (float*)d_out;

    SurfEval_fused_kernel<<<BATCH * BPB, TOUT>>>(ctrl, knot_u, out);
}